// round 6
// baseline (speedup 1.0000x reference)
#include <cuda_runtime.h>
#include <math.h>

// Problem constants
#define NN 4096
#define TT 32
#define DD 158
#define NEWS 1024
#define DGRU 128
#define GG 8
#define EE 8
#define HH 4
#define HID 64          // G*E
#define XDIM 1182       // D + NEWS
#define XKTOT 1184      // k padded to multiple of 32

// Output layout (float32, concat of tuple)
#define OFF_PRED  0
#define OFF_RW1   4096
#define OFF_HID   266240     // 4096 + 4096*64
#define OFF_TOPK  528384     // + 4096*64
#define OFF_RW2   536576     // + 4096*2

#define SPB  8          // stocks per block
#define XSTR 1188       // Xs row stride (1184 + 4)
#define HSTR 132        // h row stride (128 + 4)  <-- was the R5 OOB bug
#define KCH  32         // GEMM k-chunk

// dynamic smem layout (float offsets)
#define S_XS   0
#define S_WS   (S_XS + SPB * XSTR)          // 9504   (W chunk staging / reduce / tail scratch, 4352 floats)
#define S_MK   (S_WS + 4352)                // 13856  (mask 8x32)
#define S_INV  (S_MK + SPB * TT)            // 14112  (inv denom, 8)
#define S_H    (S_INV + SPB)                // 14120  (h rows 8x132)
#define SMEM_FLOATS (S_H + SPB * HSTR)      // 15176 floats = 60704 bytes
#define SMEM_BYTES (SMEM_FLOATS * 4)

__global__ void __launch_bounds__(256) fused_kernel(
    const float* __restrict__ price,     // [N,T,D]
    const float* __restrict__ news,      // [N,T,NEWS]
    const float* __restrict__ mask,      // [N,T]
    const float* __restrict__ router_W,  // [1182,128]
    const float* __restrict__ router_b,  // [128]
    const float* __restrict__ gate_W,    // [128,64]
    const float* __restrict__ gate_b,    // [64]
    const float* __restrict__ expert_W,  // [8,8,64]
    const float* __restrict__ expert_b,  // [8,8]
    const float* __restrict__ wq, const float* __restrict__ wq_b,
    const float* __restrict__ wk, const float* __restrict__ wk_b,
    const float* __restrict__ wv, const float* __restrict__ wv_b,
    const float* __restrict__ wo, const float* __restrict__ wo_b,
    float* __restrict__ out)
{
    extern __shared__ float smem[];
    float* Xs  = smem + S_XS;     // [SPB][XSTR]
    float* Ws  = smem + S_WS;     // [32][128] staging (reused later)
    float* smn = smem + S_MK;     // [SPB][TT]
    float* inv = smem + S_INV;    // [SPB]
    float* Hsm = smem + S_H;      // [SPB][HSTR]

    const int s0  = blockIdx.x * SPB;
    const int tid = threadIdx.x;
    const int wid = tid >> 5;
    const int lane = tid & 31;

    // ---------------- mask + denominators (warp per stock) ----------------
    {
        float mv = mask[(size_t)(s0 + wid) * TT + lane];
        smn[wid * TT + lane] = mv;
        float s = mv;
        #pragma unroll
        for (int o = 16; o > 0; o >>= 1) s += __shfl_xor_sync(0xffffffffu, s, o);
        if (lane == 0) inv[wid] = 1.0f / fmaxf(s, 1e-6f);
    }
    // zero the two pad columns
    if (tid < SPB) { Xs[tid * XSTR + XDIM] = 0.f; Xs[tid * XSTR + XDIM + 1] = 0.f; }
    __syncthreads();

    // ---------------- news aggregation (HBM streaming) ---------------------
    // thread owns dims 4*tid..4*tid+3 for every stock
    for (int s = 0; s < SPB; s++) {
        const float4* news4 = (const float4*)(news + (size_t)(s0 + s) * TT * NEWS);
        const float* ms = smn + s * TT;
        float4 acc = make_float4(0.f, 0.f, 0.f, 0.f);
        #pragma unroll 8
        for (int t = 0; t < TT; t++) {
            float4 v = news4[t * (NEWS / 4) + tid];
            float mt = ms[t];
            acc.x += mt * v.x; acc.y += mt * v.y;
            acc.z += mt * v.z; acc.w += mt * v.w;
        }
        float idn = inv[s];
        float* xr = Xs + s * XSTR + DD + 4 * tid;
        xr[0] = acc.x * idn; xr[1] = acc.y * idn;
        xr[2] = acc.z * idn; xr[3] = acc.w * idn;
    }

    // ---------------- price aggregation ------------------------------------
    for (int i = tid; i < SPB * DD; i += 256) {
        int s = i / DD;
        int d = i - s * DD;
        const float* p = price + (size_t)(s0 + s) * TT * DD + d;
        float a = 0.f;
        #pragma unroll 8
        for (int t = 0; t < TT; t++) a += p[t * DD];
        Xs[s * XSTR + d] = a * (1.0f / TT);
    }
    __syncthreads();

    // ---------------- router GEMM: h = tanh(X @ W + b) ----------------------
    // thread tile: 4 stocks x 4 cols, 4-way k-split.
    const int q  = tid >> 6;                               // k-split 0..3
    const int r  = tid & 63;
    const int sg = (tid >> 4) & 1;                         // stock group
    const int cg = (tid & 15) | (((tid >> 5) & 1) << 4);   // col group 0..31

    float acc[4][4];
    #pragma unroll
    for (int i = 0; i < 4; i++)
        #pragma unroll
        for (int j = 0; j < 4; j++) acc[i][j] = 0.f;

    const int kr = tid >> 3;            // staging row 0..31
    const int cb = (tid & 7) * 16;      // staging col base

    for (int kc = 0; kc < XKTOT; kc += KCH) {
        // stage W chunk [32][128]
        float4 w0, w1, w2, w3;
        if (kc + kr < XDIM) {
            const float* wrow = router_W + (size_t)(kc + kr) * DGRU + cb;
            w0 = *(const float4*)(wrow);
            w1 = *(const float4*)(wrow + 4);
            w2 = *(const float4*)(wrow + 8);
            w3 = *(const float4*)(wrow + 12);
        } else {
            w0 = w1 = w2 = w3 = make_float4(0.f, 0.f, 0.f, 0.f);
        }
        *(float4*)&Ws[kr * DGRU + cb +  0] = w0;
        *(float4*)&Ws[kr * DGRU + cb +  4] = w1;
        *(float4*)&Ws[kr * DGRU + cb +  8] = w2;
        *(float4*)&Ws[kr * DGRU + cb + 12] = w3;
        __syncthreads();

        #pragma unroll
        for (int kk = q * 8; kk < q * 8 + 8; kk++) {
            const int k = kc + kk;
            float x0 = Xs[(sg * 4 + 0) * XSTR + k];
            float x1 = Xs[(sg * 4 + 1) * XSTR + k];
            float x2 = Xs[(sg * 4 + 2) * XSTR + k];
            float x3 = Xs[(sg * 4 + 3) * XSTR + k];
            float4 w = *(float4*)&Ws[kk * DGRU + cg * 4];
            acc[0][0] += x0 * w.x; acc[0][1] += x0 * w.y; acc[0][2] += x0 * w.z; acc[0][3] += x0 * w.w;
            acc[1][0] += x1 * w.x; acc[1][1] += x1 * w.y; acc[1][2] += x1 * w.z; acc[1][3] += x1 * w.w;
            acc[2][0] += x2 * w.x; acc[2][1] += x2 * w.y; acc[2][2] += x2 * w.z; acc[2][3] += x2 * w.w;
            acc[3][0] += x3 * w.x; acc[3][1] += x3 * w.y; acc[3][2] += x3 * w.z; acc[3][3] += x3 * w.w;
        }
        __syncthreads();
    }

    // k-split reduction in Ws region (stride 17 to dodge conflicts)
    if (q > 0) {
        float* dst = Ws + ((q - 1) * 64 + r) * 17;
        #pragma unroll
        for (int i = 0; i < 4; i++)
            #pragma unroll
            for (int j = 0; j < 4; j++) dst[i * 4 + j] = acc[i][j];
    }
    __syncthreads();
    if (q == 0) {
        #pragma unroll
        for (int p = 0; p < 3; p++) {
            const float* src = Ws + (p * 64 + r) * 17;
            #pragma unroll
            for (int i = 0; i < 4; i++)
                #pragma unroll
                for (int j = 0; j < 4; j++) acc[i][j] += src[i * 4 + j];
        }
        float4 b = *(const float4*)&router_b[cg * 4];
        #pragma unroll
        for (int i = 0; i < 4; i++) {
            float* hr = Hsm + (sg * 4 + i) * HSTR + cg * 4;
            hr[0] = tanhf(acc[i][0] + b.x);
            hr[1] = tanhf(acc[i][1] + b.y);
            hr[2] = tanhf(acc[i][2] + b.z);
            hr[3] = tanhf(acc[i][3] + b.w);
        }
    }
    __syncthreads();

    // ---------------- tail: gate -> top2 -> experts -> outputs -------------
    float* Hid = Ws;            // [8][64]
    float* Out = Ws + 512;      // [8][64]
    int*   Si1 = (int*)(Ws + 1024);
    int*   Si2 = (int*)(Ws + 1032);
    float* Sw1 = Ws + 1040;
    float* Sw2 = Ws + 1048;

    // gate: thread = (stock tid>>5, 2 cols)
    {
        int s  = tid >> 5;
        int c2 = (tid & 31) * 2;
        float g0 = gate_b[c2], g1 = gate_b[c2 + 1];
        const float* hr = Hsm + s * HSTR;
        #pragma unroll 8
        for (int j = 0; j < DGRU; j++) {
            float hv = hr[j];
            float2 w = *(const float2*)&gate_W[j * HID + c2];
            g0 += hv * w.x; g1 += hv * w.y;
        }
        Hid[s * HID + c2]     = g0;
        Hid[s * HID + c2 + 1] = g1;
    }
    __syncthreads();

    // top-2 + softmax (thread per stock)
    if (tid < SPB) {
        int s = tid;
        float best1 = -3.4e38f; int i1 = 0;
        for (int c = 0; c < HID; c++) {
            float v = Hid[s * HID + c];
            if (v > best1) { best1 = v; i1 = c; }
        }
        float best2 = -3.4e38f; int i2 = 0;
        for (int c = 0; c < HID; c++) {
            if (c == i1) continue;
            float v = Hid[s * HID + c];
            if (v > best2) { best2 = v; i2 = c; }
        }
        float e2 = expf(best2 - best1);
        float rr = 1.0f / (1.0f + e2);
        Si1[s] = i1; Si2[s] = i2;
        Sw1[s] = rr; Sw2[s] = e2 * rr;
    }

    // experts + attention: thread = (stock, group), 64 active
    if (tid < SPB * GG) {
        int s = tid >> 3;
        int g = tid & 7;
        float eo[EE];
        #pragma unroll
        for (int e = 0; e < EE; e++) {
            float a = expert_b[g * EE + e];
            const float4* wr = (const float4*)&expert_W[((size_t)(g * EE + e)) * HID];
            const float4* hrr = (const float4*)&Hid[s * HID];
            #pragma unroll
            for (int h4 = 0; h4 < HID / 4; h4++) {
                float4 w = wr[h4];
                float4 h = hrr[h4];
                a += w.x * h.x + w.y * h.y + w.z * h.z + w.w * h.w;
            }
            eo[e] = a;
        }
        float qv_[EE], kv_[EE], vv_[EE];
        #pragma unroll
        for (int f = 0; f < EE; f++) {
            float aq = wq_b[g * EE + f];
            float ak = wk_b[g * EE + f];
            float av = wv_b[g * EE + f];
            #pragma unroll
            for (int e = 0; e < EE; e++) {
                aq += eo[e] * wq[(g * EE + f) * EE + e];
                ak += eo[e] * wk[(g * EE + f) * EE + e];
                av += eo[e] * wv[(g * EE + f) * EE + e];
            }
            qv_[f] = aq; kv_[f] = ak; vv_[f] = av;
        }
        const float isq = 0.70710678118654752f;
        float att[EE];
        #pragma unroll
        for (int d = 0; d < 2; d++) {
            float sc0 = 0.f, sc1 = 0.f;
            #pragma unroll
            for (int h = 0; h < HH; h++) {
                float qq = qv_[h * 2 + d];
                sc0 += qq * kv_[h * 2 + 0];
                sc1 += qq * kv_[h * 2 + 1];
            }
            sc0 *= isq; sc1 *= isq;
            float mx = fmaxf(sc0, sc1);
            float p0 = expf(sc0 - mx), p1 = expf(sc1 - mx);
            float rn = 1.0f / (p0 + p1);
            p0 *= rn; p1 *= rn;
            #pragma unroll
            for (int h = 0; h < HH; h++)
                att[h * 2 + d] = p0 * vv_[h * 2 + 0] + p1 * vv_[h * 2 + 1];
        }
        #pragma unroll
        for (int f = 0; f < EE; f++) {
            float a = wo_b[g * EE + f];
            #pragma unroll
            for (int e = 0; e < EE; e++)
                a += att[e] * wo[(g * EE + f) * EE + e];
            Out[s * HID + g * EE + f] = a;
        }
    }
    __syncthreads();

    // predictions + topk
    if (tid < SPB) {
        int s = tid;
        int i1 = Si1[s], i2 = Si2[s];
        float pred = Sw1[s] * Out[s * HID + i1] + Sw2[s] * Out[s * HID + i2];
        out[OFF_PRED + s0 + s] = pred;
        out[OFF_TOPK + (size_t)(s0 + s) * 2 + 0] = (float)i1;
        out[OFF_TOPK + (size_t)(s0 + s) * 2 + 1] = (float)i2;
    }

    // hidden + routing_weights (x2): 8 stocks x 64 cols = 128 float4
    if (tid < 128) {
        int s = tid >> 4;
        int c = (tid & 15) * 4;
        float4 hv = *(float4*)&Hid[s * HID + c];
        *(float4*)&out[OFF_HID + (size_t)(s0 + s) * HID + c] = hv;

        int i1 = Si1[s], i2 = Si2[s];
        float w1 = Sw1[s], w2 = Sw2[s];
        float4 rw;
        rw.x = (c + 0 == i1) ? w1 : (c + 0 == i2) ? w2 : 0.f;
        rw.y = (c + 1 == i1) ? w1 : (c + 1 == i2) ? w2 : 0.f;
        rw.z = (c + 2 == i1) ? w1 : (c + 2 == i2) ? w2 : 0.f;
        rw.w = (c + 3 == i1) ? w1 : (c + 3 == i2) ? w2 : 0.f;
        *(float4*)&out[OFF_RW1 + (size_t)(s0 + s) * HID + c] = rw;
        *(float4*)&out[OFF_RW2 + (size_t)(s0 + s) * HID + c] = rw;
    }
}

// ---------------------------------------------------------------------------
extern "C" void kernel_launch(void* const* d_in, const int* in_sizes, int n_in,
                              void* d_out, int out_size) {
    const float* price    = (const float*)d_in[0];
    const float* news     = (const float*)d_in[1];
    const float* mask     = (const float*)d_in[2];
    const float* router_W = (const float*)d_in[3];
    const float* router_b = (const float*)d_in[4];
    const float* gate_W   = (const float*)d_in[5];
    const float* gate_b   = (const float*)d_in[6];
    const float* expert_W = (const float*)d_in[7];
    const float* expert_b = (const float*)d_in[8];
    const float* wq   = (const float*)d_in[9];
    const float* wq_b = (const float*)d_in[10];
    const float* wk   = (const float*)d_in[11];
    const float* wk_b = (const float*)d_in[12];
    const float* wv   = (const float*)d_in[13];
    const float* wv_b = (const float*)d_in[14];
    const float* wo   = (const float*)d_in[15];
    const float* wo_b = (const float*)d_in[16];
    float* out = (float*)d_out;

    static int configured = 0;
    if (!configured) {
        cudaFuncSetAttribute(fused_kernel,
                             cudaFuncAttributeMaxDynamicSharedMemorySize, SMEM_BYTES);
        configured = 1;
    }
    fused_kernel<<<NN / SPB, 256, SMEM_BYTES>>>(
        price, news, mask, router_W, router_b, gate_W, gate_b,
        expert_W, expert_b, wq, wq_b, wk, wk_b, wv, wv_b, wo, wo_b, out);
}